// round 10
// baseline (speedup 1.0000x reference)
#include <cuda_runtime.h>
#include <cuda_fp16.h>
#include <cstdint>

// ===================== problem constants =====================
constexpr int B_  = 8;
constexpr int LQ_ = 2048;
constexpr int LK_ = 2048;
constexpr int D_  = 128;

constexpr int BM = 64;     // q rows per CTA
constexpr int BN = 64;     // kv rows per iteration
constexpr int NT = LK_ / BN; // 32 kv tiles

constexpr float SCALE = 0.08838834764831845f; // 1/sqrt(128)
constexpr float HALF_SCALE = 0.5f * SCALE;    // folded into Q at prep time

// ---- smem: swizzled, no padding. Row = 128 fp16 = 256B.
constexpr int SM_Q        = 0;
constexpr int TILE_BYTES  = 64 * 256;            // 16384 (one 64x128 fp16 tile)
constexpr int SM_KV       = TILE_BYTES;          // Q occupies one tile
constexpr int STAGE_BYTES = 2 * TILE_BYTES;      // K + V
constexpr int NSTAGE      = 3;
constexpr int SMEM_BYTES  = SM_KV + NSTAGE * STAGE_BYTES; // 114688 -> 2 CTAs/SM

// ===================== device scratch (fp16 casts) =====================
__device__ __half g_q[B_ * LQ_ * D_];   // pre-scaled by HALF_SCALE
__device__ __half g_k[B_ * LK_ * D_];
__device__ __half g_v[B_ * LK_ * D_];

// ===================== small asm helpers =====================
__device__ __forceinline__ void cp_async16(uint32_t dst, const void* src) {
    asm volatile("cp.async.cg.shared.global [%0], [%1], 16;" :: "r"(dst), "l"(src));
}
__device__ __forceinline__ void cp_commit() {
    asm volatile("cp.async.commit_group;");
}
template <int N>
__device__ __forceinline__ void cp_wait() {
    asm volatile("cp.async.wait_group %0;" :: "n"(N));
}
__device__ __forceinline__ void ldsm4(uint32_t* r, uint32_t addr) {
    asm volatile("ldmatrix.sync.aligned.m8n8.x4.shared.b16 {%0,%1,%2,%3}, [%4];"
                 : "=r"(r[0]), "=r"(r[1]), "=r"(r[2]), "=r"(r[3]) : "r"(addr));
}
__device__ __forceinline__ void ldsm4t(uint32_t* r, uint32_t addr) {
    asm volatile("ldmatrix.sync.aligned.m8n8.x4.trans.shared.b16 {%0,%1,%2,%3}, [%4];"
                 : "=r"(r[0]), "=r"(r[1]), "=r"(r[2]), "=r"(r[3]) : "r"(addr));
}
__device__ __forceinline__ void mma16816(float* c, const uint32_t* a, uint32_t b0, uint32_t b1) {
    asm volatile(
        "mma.sync.aligned.m16n8k16.row.col.f32.f16.f16.f32 "
        "{%0,%1,%2,%3}, {%4,%5,%6,%7}, {%8,%9}, {%0,%1,%2,%3};"
        : "+f"(c[0]), "+f"(c[1]), "+f"(c[2]), "+f"(c[3])
        : "r"(a[0]), "r"(a[1]), "r"(a[2]), "r"(a[3]), "r"(b0), "r"(b1));
}
// Q pre-scaled by SCALE/2: sigmoid(x) = 0.5*tanh(x/2)+0.5, tanh.approx on sacc.
__device__ __forceinline__ float sigmoid_fast(float s) {
    float t;
    asm("tanh.approx.f32 %0, %1;" : "=f"(t) : "f"(s));
    return fmaf(t, 0.5f, 0.5f);
}
__device__ __forceinline__ uint32_t pack2h(float x, float y) {
    __half2 h = __floats2half2_rn(x, y);
    return *reinterpret_cast<uint32_t*>(&h);
}
// swizzled byte offset within a 64x128 fp16 tile: row 256B, 16B unit ^= row&7
__device__ __forceinline__ uint32_t sw_off(int row, int c16) {
    return (uint32_t)(row * 256 + ((c16 ^ (row & 7)) << 4));
}

// ===================== prep: fp32 -> fp16 (Q pre-scaled), 8 elems/thread =====================
__global__ void split_kernel(const float* __restrict__ q,
                             const float* __restrict__ k,
                             const float* __restrict__ v) {
    const int t = blockIdx.y;
    const float* s = (t == 0) ? q : (t == 1) ? k : v;
    __half* H = (t == 0) ? g_q : (t == 1) ? g_k : g_v;
    const float sc = (t == 0) ? HALF_SCALE : 1.0f;
    const int i = (blockIdx.x * blockDim.x + threadIdx.x) * 8;
    float4 a = *reinterpret_cast<const float4*>(s + i);
    float4 b = *reinterpret_cast<const float4*>(s + i + 4);
    __half2 h0 = __floats2half2_rn(a.x * sc, a.y * sc);
    __half2 h1 = __floats2half2_rn(a.z * sc, a.w * sc);
    __half2 h2 = __floats2half2_rn(b.x * sc, b.y * sc);
    __half2 h3 = __floats2half2_rn(b.z * sc, b.w * sc);
    uint4 o;
    o.x = *reinterpret_cast<uint32_t*>(&h0);
    o.y = *reinterpret_cast<uint32_t*>(&h1);
    o.z = *reinterpret_cast<uint32_t*>(&h2);
    o.w = *reinterpret_cast<uint32_t*>(&h3);
    *reinterpret_cast<uint4*>(H + i) = o;
}

// ===================== kv tile loader (K+V, 64 rows each, swizzled) =====================
__device__ __forceinline__ void load_kv(uint32_t smb, int b, int kt, int stg, int tid) {
    const size_t base = ((size_t)b * LK_ + (size_t)kt * BN) * D_;
    const __half* gs[2] = { g_k + base, g_v + base };
    const uint32_t sbase = smb + (uint32_t)(SM_KV + stg * STAGE_BYTES);
#pragma unroll
    for (int a = 0; a < 2; a++) {
#pragma unroll
        for (int tt = 0; tt < 4; tt++) {
            int idx = tt * 256 + tid;          // 1024 chunks of 16B per tile
            int row = idx >> 4, c16 = idx & 15;
            cp_async16(sbase + (uint32_t)(a * TILE_BYTES) + sw_off(row, c16),
                       gs[a] + (size_t)row * D_ + c16 * 8);
        }
    }
}

// ===================== main attention kernel =====================
// 8 warps: mg = w&3 -> 16 q-rows, ng = w>>2 -> 32 of 64 kv cols.
// Q held in registers; 3-stage cp.async pipeline, one __syncthreads per iter.
__global__ void __launch_bounds__(256, 2)
attn_kernel(const int* __restrict__ mask, float* __restrict__ out) {
    extern __shared__ __half sm[];
    const int tid  = threadIdx.x;
    const int lane = tid & 31;
    const int w    = tid >> 5;
    const int mg   = w & 3;
    const int ng   = w >> 2;
    const int qt   = blockIdx.x;
    const int b    = blockIdx.y;
    const int qbase = qt * BM;

    const uint32_t smb = (uint32_t)__cvta_generic_to_shared(sm);

    // ---- prologue: G0 = Q + KV tile0, G1 = KV tile1
    {
        const __half* gq = g_q + ((size_t)b * LQ_ + qbase) * D_;
#pragma unroll
        for (int tt = 0; tt < 4; tt++) {
            int idx = tt * 256 + tid;
            int row = idx >> 4, c16 = idx & 15;
            cp_async16(smb + SM_Q + sw_off(row, c16), gq + (size_t)row * D_ + c16 * 8);
        }
    }
    load_kv(smb, b, 0, 0, tid);
    cp_commit();                       // G0
    load_kv(smb, b, 1, 1, tid);
    cp_commit();                       // G1

    // ---- per-thread fragment coordinates
    const int l8  = lane & 7;
    const int grp = lane >> 3;
    const int hi  = lane >> 4;                 // Q c16 half
    const int rowq = mg * 16 + (lane & 15);
    const uint32_t qrow = smb + SM_Q + (uint32_t)(rowq * 256);
    const int qx = rowq & 7;
    const int g1 = grp & 1;
    const int ncol0 = ng * 32;
    const int krow0 = ncol0 + (grp >> 1) * 8 + l8;      // K fragment row (+jp*16)
    const int vrow0 = ncol0 + g1 * 8 + l8;              // V fragment row (+s*16)
    const int vc0   = grp >> 1;                         // V c16 base (+jp*2)

    // ---- mask / output row mapping
    const int g0 = qbase + mg * 16 + (lane >> 2);
    const int q2 = (lane & 3) * 2;
    const int* mrow0 = mask + ((size_t)b * LQ_ + g0) * LK_;
    const int* mrow1 = mrow0 + (size_t)8 * LK_;

    // ---- wait for G0 (Q + KV0) and load Q fragments into registers, once
    cp_wait<1>();
    __syncthreads();
    uint32_t qa[8][4];
#pragma unroll
    for (int k16 = 0; k16 < 8; k16++)
        ldsm4(qa[k16], qrow + (uint32_t)((((k16 * 2 + hi) ^ qx) << 4)));

    float oacc[16][4];
#pragma unroll
    for (int i = 0; i < 16; i++)
#pragma unroll
        for (int e = 0; e < 4; e++) oacc[i][e] = 0.0f;

#pragma unroll 1
    for (int kt = 0; kt < NT; ++kt) {
        // mask rows r: issue early (deep latency hiding)
        int2 m0[4];
#pragma unroll
        for (int j = 0; j < 4; j++) {
            int col = kt * BN + ncol0 + j * 8 + q2;
            m0[j] = *reinterpret_cast<const int2*>(mrow0 + col);
        }

        if (kt + 1 < NT) cp_wait<1>(); else cp_wait<0>();
        __syncthreads();   // stage kt visible; iter kt-1 reads finished

        if (kt + 2 < NT) {
            load_kv(smb, b, kt + 2, (kt + 2) % 3, tid);
            cp_commit();
        }

        const uint32_t sK = smb + (uint32_t)(SM_KV + (kt % 3) * STAGE_BYTES);
        const uint32_t sV = sK + (uint32_t)TILE_BYTES;

        // ======== S = Q K^T over this warp's 16x32 block (Q in regs) ========
        float sacc[4][4];
#pragma unroll
        for (int j = 0; j < 4; j++)
#pragma unroll
            for (int e = 0; e < 4; e++) sacc[j][e] = 0.0f;

#pragma unroll
        for (int k16 = 0; k16 < 4; k16++) {
#pragma unroll
            for (int jp = 0; jp < 2; jp++) {
                uint32_t bb[4];
                ldsm4(bb, sK + (uint32_t)((krow0 + jp * 16) * 256 +
                                          (((k16 * 2 + g1) ^ l8) << 4)));
                mma16816(sacc[2 * jp],     qa[k16], bb[0], bb[1]);
                mma16816(sacc[2 * jp + 1], qa[k16], bb[2], bb[3]);
            }
        }

        // mask rows r+8: issue midway (staggered register residency)
        int2 m1[4];
#pragma unroll
        for (int j = 0; j < 4; j++) {
            int col = kt * BN + ncol0 + j * 8 + q2;
            m1[j] = *reinterpret_cast<const int2*>(mrow1 + col);
        }

#pragma unroll
        for (int k16 = 4; k16 < 8; k16++) {
#pragma unroll
            for (int jp = 0; jp < 2; jp++) {
                uint32_t bb[4];
                ldsm4(bb, sK + (uint32_t)((krow0 + jp * 16) * 256 +
                                          (((k16 * 2 + g1) ^ l8) << 4)));
                mma16816(sacc[2 * jp],     qa[k16], bb[0], bb[1]);
                mma16816(sacc[2 * jp + 1], qa[k16], bb[2], bb[3]);
            }
        }

        // ======== P = mask ? 0 : sigmoid (tanh.approx, scale pre-folded) ========
#pragma unroll
        for (int j = 0; j < 4; j++) {
            sacc[j][0] = m0[j].x ? 0.0f : sigmoid_fast(sacc[j][0]);
            sacc[j][1] = m0[j].y ? 0.0f : sigmoid_fast(sacc[j][1]);
            sacc[j][2] = m1[j].x ? 0.0f : sigmoid_fast(sacc[j][2]);
            sacc[j][3] = m1[j].y ? 0.0f : sigmoid_fast(sacc[j][3]);
        }

        // ======== O += P V over this warp's 32 kv rows ========
#pragma unroll
        for (int s = 0; s < 2; s++) {
            uint32_t pa[4];
            pa[0] = pack2h(sacc[2 * s][0],     sacc[2 * s][1]);
            pa[1] = pack2h(sacc[2 * s][2],     sacc[2 * s][3]);
            pa[2] = pack2h(sacc[2 * s + 1][0], sacc[2 * s + 1][1]);
            pa[3] = pack2h(sacc[2 * s + 1][2], sacc[2 * s + 1][3]);
            const uint32_t vr = sV + (uint32_t)((vrow0 + s * 16) * 256);
#pragma unroll
            for (int jp = 0; jp < 8; jp++) {
                uint32_t vv[4];
                ldsm4t(vv, vr + (uint32_t)((((vc0 + jp * 2) ^ l8) << 4)));
                mma16816(oacc[2 * jp],     pa, vv[0], vv[1]);
                mma16816(oacc[2 * jp + 1], pa, vv[2], vv[3]);
            }
        }
        // no trailing barrier: next iter's top barrier fences stage reuse
    }

    // ---- reduce the two kv-column halves through smem, then write O
    __syncthreads();   // all warps out of the mainloop before smem reuse
    float* smf = reinterpret_cast<float*>(sm);
    const int r0 = lane >> 2;
    if (ng == 1) {
#pragma unroll
        for (int jd = 0; jd < 16; jd++) {
            int col = jd * 8 + q2;
            float* p0 = smf + (mg * 16 + r0) * 128 + col;
            float* p1 = smf + (mg * 16 + r0 + 8) * 128 + col;
            p0[0] = oacc[jd][0]; p0[1] = oacc[jd][1];
            p1[0] = oacc[jd][2]; p1[1] = oacc[jd][3];
        }
    }
    __syncthreads();
    if (ng == 0) {
        float* o0 = out + ((size_t)b * LQ_ + g0) * D_;
        float* o1 = o0 + (size_t)8 * D_;
#pragma unroll
        for (int jd = 0; jd < 16; jd++) {
            int col = jd * 8 + q2;
            const float* p0 = smf + (mg * 16 + r0) * 128 + col;
            const float* p1 = smf + (mg * 16 + r0 + 8) * 128 + col;
            *reinterpret_cast<float2*>(o0 + col) =
                make_float2(oacc[jd][0] + p0[0], oacc[jd][1] + p0[1]);
            *reinterpret_cast<float2*>(o1 + col) =
                make_float2(oacc[jd][2] + p1[0], oacc[jd][3] + p1[1]);
        }
    }
}

// ===================== launch =====================
extern "C" void kernel_launch(void* const* d_in, const int* in_sizes, int n_in,
                              void* d_out, int out_size) {
    const float* q    = (const float*)d_in[0];
    const float* k    = (const float*)d_in[1];
    const float* v    = (const float*)d_in[2];
    const int*   mask = (const int*)d_in[3];
    float*       out  = (float*)d_out;

    cudaFuncSetAttribute(attn_kernel, cudaFuncAttributeMaxDynamicSharedMemorySize, SMEM_BYTES);

    // convert q,k,v to fp16 (Q pre-scaled by SCALE/2)
    split_kernel<<<dim3((B_ * LQ_ * D_ / 8) / 256, 3), 256>>>(q, k, v);

    // fused sigmoid-attention: 256 CTAs, 2 CTAs/SM, Q-in-regs, 3-stage pipeline
    attn_kernel<<<dim3(LQ_ / BM, B_), 256, SMEM_BYTES>>>(mask, out);
}

// round 11
// speedup vs baseline: 1.3426x; 1.3426x over previous
#include <cuda_runtime.h>
#include <cuda_fp16.h>
#include <cstdint>

// ===================== problem constants =====================
constexpr int B_  = 8;
constexpr int LQ_ = 2048;
constexpr int LK_ = 2048;
constexpr int D_  = 128;

constexpr int BM = 64;     // q rows per CTA
constexpr int BN = 64;     // kv rows per iteration
constexpr int NT = LK_ / BN; // 32 kv tiles

constexpr float SCALE = 0.08838834764831845f; // 1/sqrt(128)
constexpr float HALF_SCALE = 0.5f * SCALE;    // folded into Q at prep time

// ---- smem: swizzled, no padding. Row = 128 fp16 = 256B.
constexpr int SM_Q        = 0;
constexpr int TILE_BYTES  = 64 * 256;            // 16384 (one 64x128 fp16 tile)
constexpr int SM_KV       = TILE_BYTES;          // Q occupies one tile
constexpr int STAGE_BYTES = 2 * TILE_BYTES;      // K + V
constexpr int NSTAGE      = 3;
constexpr int SMEM_BYTES  = SM_KV + NSTAGE * STAGE_BYTES; // 114688 -> 2 CTAs/SM

// ===================== device scratch (fp16 casts) =====================
__device__ __half g_q[B_ * LQ_ * D_];   // pre-scaled by HALF_SCALE
__device__ __half g_k[B_ * LK_ * D_];
__device__ __half g_v[B_ * LK_ * D_];

// ===================== small asm helpers =====================
__device__ __forceinline__ void cp_async16(uint32_t dst, const void* src) {
    asm volatile("cp.async.cg.shared.global [%0], [%1], 16;" :: "r"(dst), "l"(src));
}
__device__ __forceinline__ void cp_commit() {
    asm volatile("cp.async.commit_group;");
}
template <int N>
__device__ __forceinline__ void cp_wait() {
    asm volatile("cp.async.wait_group %0;" :: "n"(N));
}
__device__ __forceinline__ void ldsm4(uint32_t* r, uint32_t addr) {
    asm volatile("ldmatrix.sync.aligned.m8n8.x4.shared.b16 {%0,%1,%2,%3}, [%4];"
                 : "=r"(r[0]), "=r"(r[1]), "=r"(r[2]), "=r"(r[3]) : "r"(addr));
}
__device__ __forceinline__ void ldsm4t(uint32_t* r, uint32_t addr) {
    asm volatile("ldmatrix.sync.aligned.m8n8.x4.trans.shared.b16 {%0,%1,%2,%3}, [%4];"
                 : "=r"(r[0]), "=r"(r[1]), "=r"(r[2]), "=r"(r[3]) : "r"(addr));
}
__device__ __forceinline__ void mma16816(float* c, const uint32_t* a, uint32_t b0, uint32_t b1) {
    asm volatile(
        "mma.sync.aligned.m16n8k16.row.col.f32.f16.f16.f32 "
        "{%0,%1,%2,%3}, {%4,%5,%6,%7}, {%8,%9}, {%0,%1,%2,%3};"
        : "+f"(c[0]), "+f"(c[1]), "+f"(c[2]), "+f"(c[3])
        : "r"(a[0]), "r"(a[1]), "r"(a[2]), "r"(a[3]), "r"(b0), "r"(b1));
}
// Q pre-scaled by SCALE/2: sigmoid(x) = 0.5*tanh(x/2)+0.5, tanh.approx on sacc.
__device__ __forceinline__ float sigmoid_fast(float s) {
    float t;
    asm("tanh.approx.f32 %0, %1;" : "=f"(t) : "f"(s));
    return fmaf(t, 0.5f, 0.5f);
}
__device__ __forceinline__ uint32_t pack2h(float x, float y) {
    __half2 h = __floats2half2_rn(x, y);
    return *reinterpret_cast<uint32_t*>(&h);
}
// swizzled byte offset within a 64x128 fp16 tile: row 256B, 16B unit ^= row&7
__device__ __forceinline__ uint32_t sw_off(int row, int c16) {
    return (uint32_t)(row * 256 + ((c16 ^ (row & 7)) << 4));
}

// ===================== prep: fp32 -> fp16 (Q pre-scaled), 8 elems/thread =====================
__global__ void split_kernel(const float* __restrict__ q,
                             const float* __restrict__ k,
                             const float* __restrict__ v) {
    const int t = blockIdx.y;
    const float* s = (t == 0) ? q : (t == 1) ? k : v;
    __half* H = (t == 0) ? g_q : (t == 1) ? g_k : g_v;
    const float sc = (t == 0) ? HALF_SCALE : 1.0f;
    const int i = (blockIdx.x * blockDim.x + threadIdx.x) * 8;
    float4 a = *reinterpret_cast<const float4*>(s + i);
    float4 b = *reinterpret_cast<const float4*>(s + i + 4);
    __half2 h0 = __floats2half2_rn(a.x * sc, a.y * sc);
    __half2 h1 = __floats2half2_rn(a.z * sc, a.w * sc);
    __half2 h2 = __floats2half2_rn(b.x * sc, b.y * sc);
    __half2 h3 = __floats2half2_rn(b.z * sc, b.w * sc);
    uint4 o;
    o.x = *reinterpret_cast<uint32_t*>(&h0);
    o.y = *reinterpret_cast<uint32_t*>(&h1);
    o.z = *reinterpret_cast<uint32_t*>(&h2);
    o.w = *reinterpret_cast<uint32_t*>(&h3);
    *reinterpret_cast<uint4*>(H + i) = o;
}

// ===================== kv tile loader (K+V, 64 rows each, swizzled) =====================
__device__ __forceinline__ void load_kv(uint32_t smb, int b, int kt, int stg, int tid) {
    const size_t base = ((size_t)b * LK_ + (size_t)kt * BN) * D_;
    const __half* gs[2] = { g_k + base, g_v + base };
    const uint32_t sbase = smb + (uint32_t)(SM_KV + stg * STAGE_BYTES);
#pragma unroll
    for (int a = 0; a < 2; a++) {
#pragma unroll
        for (int tt = 0; tt < 4; tt++) {
            int idx = tt * 256 + tid;          // 1024 chunks of 16B per tile
            int row = idx >> 4, c16 = idx & 15;
            cp_async16(sbase + (uint32_t)(a * TILE_BYTES) + sw_off(row, c16),
                       gs[a] + (size_t)row * D_ + c16 * 8);
        }
    }
}

// ===================== main attention kernel =====================
// 8 warps: mg = w&3 -> 16 q-rows, ng = w>>2 -> 32 of 64 kv cols.
// 3-stage cp.async pipeline, one __syncthreads per iteration.
__global__ void __launch_bounds__(256, 2)
attn_kernel(const int* __restrict__ mask, float* __restrict__ out) {
    extern __shared__ __half sm[];
    const int tid  = threadIdx.x;
    const int lane = tid & 31;
    const int w    = tid >> 5;
    const int mg   = w & 3;
    const int ng   = w >> 2;
    const int qt   = blockIdx.x;
    const int b    = blockIdx.y;
    const int qbase = qt * BM;

    const uint32_t smb = (uint32_t)__cvta_generic_to_shared(sm);

    // ---- prologue: G0 = Q + KV tile0, G1 = KV tile1
    {
        const __half* gq = g_q + ((size_t)b * LQ_ + qbase) * D_;
#pragma unroll
        for (int tt = 0; tt < 4; tt++) {
            int idx = tt * 256 + tid;
            int row = idx >> 4, c16 = idx & 15;
            cp_async16(smb + SM_Q + sw_off(row, c16), gq + (size_t)row * D_ + c16 * 8);
        }
    }
    load_kv(smb, b, 0, 0, tid);
    cp_commit();                       // G0
    load_kv(smb, b, 1, 1, tid);
    cp_commit();                       // G1

    // ---- per-thread fragment coordinates (all loop-invariant)
    const int l8  = lane & 7;
    const int grp = lane >> 3;
    const int hi  = lane >> 4;                 // Q c16 half
    const int rowq = mg * 16 + (lane & 15);
    const uint32_t qrow = smb + SM_Q + (uint32_t)(rowq * 256);
    const int qx = rowq & 7;
    const int g1 = grp & 1;
    const int ncol0 = ng * 32;
    const uint32_t kbyte0 = (uint32_t)((ncol0 + (grp >> 1) * 8 + l8) * 256); // + jp*4096
    const uint32_t vbyte0 = (uint32_t)((ncol0 + g1 * 8 + l8) * 256);        // + s*4096
    const int vc0   = grp >> 1;                                             // + jp*2

    // ---- mask / output row mapping
    const int g0 = qbase + mg * 16 + (lane >> 2);
    const int q2 = (lane & 3) * 2;
    const int* mrow0 = mask + ((size_t)b * LQ_ + g0) * LK_;
    const int* mrow1 = mrow0 + (size_t)8 * LK_;

    float oacc[16][4];
#pragma unroll
    for (int i = 0; i < 16; i++)
#pragma unroll
        for (int e = 0; e < 4; e++) oacc[i][e] = 0.0f;

    int st  = 0;   // stage of current tile kt
    int st2 = 2;   // stage of tile kt+2 (prefetch target)

#pragma unroll 1
    for (int kt = 0; kt < NT; ++kt) {
        // mask LDGs first (independent; latency hides under wait+MMAs)
        int2 m0[4], m1[4];
#pragma unroll
        for (int j = 0; j < 4; j++) {
            int col = kt * BN + ncol0 + j * 8 + q2;
            m0[j] = *reinterpret_cast<const int2*>(mrow0 + col);
            m1[j] = *reinterpret_cast<const int2*>(mrow1 + col);
        }

        if (kt + 1 < NT) cp_wait<1>(); else cp_wait<0>();
        __syncthreads();   // stage kt visible to all; iter kt-1 reads finished

        if (kt + 2 < NT) {
            load_kv(smb, b, kt + 2, st2, tid);
            cp_commit();
        }

        const uint32_t sK = smb + (uint32_t)SM_KV + (uint32_t)(st * STAGE_BYTES);
        const uint32_t sV = sK + (uint32_t)TILE_BYTES;
        // advance stage counters without division
        st  = (st  == 2) ? 0 : st  + 1;
        st2 = (st2 == 2) ? 0 : st2 + 1;

        // ======== S = Q K^T over this warp's 16x32 block ========
        float sacc[4][4];
#pragma unroll
        for (int j = 0; j < 4; j++)
#pragma unroll
            for (int e = 0; e < 4; e++) sacc[j][e] = 0.0f;

#pragma unroll
        for (int k16 = 0; k16 < 8; k16++) {
            uint32_t a[4];
            ldsm4(a, qrow + (uint32_t)((((k16 * 2 + hi) ^ qx) << 4)));
#pragma unroll
            for (int jp = 0; jp < 2; jp++) {
                uint32_t bb[4];
                ldsm4(bb, sK + kbyte0 + (uint32_t)(jp * 4096) +
                          (uint32_t)((((k16 * 2 + g1) ^ l8) << 4)));
                mma16816(sacc[2 * jp],     a, bb[0], bb[1]);
                mma16816(sacc[2 * jp + 1], a, bb[2], bb[3]);
            }
        }

        // ======== P = mask ? 0 : sigmoid (tanh.approx, scale pre-folded) ========
#pragma unroll
        for (int j = 0; j < 4; j++) {
            sacc[j][0] = m0[j].x ? 0.0f : sigmoid_fast(sacc[j][0]);
            sacc[j][1] = m0[j].y ? 0.0f : sigmoid_fast(sacc[j][1]);
            sacc[j][2] = m1[j].x ? 0.0f : sigmoid_fast(sacc[j][2]);
            sacc[j][3] = m1[j].y ? 0.0f : sigmoid_fast(sacc[j][3]);
        }

        // ======== O += P V over this warp's 32 kv rows ========
#pragma unroll
        for (int s = 0; s < 2; s++) {
            uint32_t pa[4];
            pa[0] = pack2h(sacc[2 * s][0],     sacc[2 * s][1]);
            pa[1] = pack2h(sacc[2 * s][2],     sacc[2 * s][3]);
            pa[2] = pack2h(sacc[2 * s + 1][0], sacc[2 * s + 1][1]);
            pa[3] = pack2h(sacc[2 * s + 1][2], sacc[2 * s + 1][3]);
            const uint32_t vr = sV + vbyte0 + (uint32_t)(s * 4096);
#pragma unroll
            for (int jp = 0; jp < 8; jp++) {
                uint32_t vv[4];
                ldsm4t(vv, vr + (uint32_t)((((vc0 + jp * 2) ^ l8) << 4)));
                mma16816(oacc[2 * jp],     pa, vv[0], vv[1]);
                mma16816(oacc[2 * jp + 1], pa, vv[2], vv[3]);
            }
        }
        // no trailing barrier: next iter's top barrier fences stage reuse
    }

    // ---- reduce the two kv-column halves through smem, then write O
    __syncthreads();   // all warps out of the mainloop before smem reuse
    float* smf = reinterpret_cast<float*>(sm);
    const int r0 = lane >> 2;
    if (ng == 1) {
#pragma unroll
        for (int jd = 0; jd < 16; jd++) {
            int col = jd * 8 + q2;
            float* p0 = smf + (mg * 16 + r0) * 128 + col;
            float* p1 = smf + (mg * 16 + r0 + 8) * 128 + col;
            p0[0] = oacc[jd][0]; p0[1] = oacc[jd][1];
            p1[0] = oacc[jd][2]; p1[1] = oacc[jd][3];
        }
    }
    __syncthreads();
    if (ng == 0) {
        float* o0 = out + ((size_t)b * LQ_ + g0) * D_;
        float* o1 = o0 + (size_t)8 * D_;
#pragma unroll
        for (int jd = 0; jd < 16; jd++) {
            int col = jd * 8 + q2;
            const float* p0 = smf + (mg * 16 + r0) * 128 + col;
            const float* p1 = smf + (mg * 16 + r0 + 8) * 128 + col;
            *reinterpret_cast<float2*>(o0 + col) =
                make_float2(oacc[jd][0] + p0[0], oacc[jd][1] + p0[1]);
            *reinterpret_cast<float2*>(o1 + col) =
                make_float2(oacc[jd][2] + p1[0], oacc[jd][3] + p1[1]);
        }
    }
}

// ===================== launch =====================
extern "C" void kernel_launch(void* const* d_in, const int* in_sizes, int n_in,
                              void* d_out, int out_size) {
    const float* q    = (const float*)d_in[0];
    const float* k    = (const float*)d_in[1];
    const float* v    = (const float*)d_in[2];
    const int*   mask = (const int*)d_in[3];
    float*       out  = (float*)d_out;

    cudaFuncSetAttribute(attn_kernel, cudaFuncAttributeMaxDynamicSharedMemorySize, SMEM_BYTES);

    // convert q,k,v to fp16 (Q pre-scaled by SCALE/2)
    split_kernel<<<dim3((B_ * LQ_ * D_ / 8) / 256, 3), 256>>>(q, k, v);

    // fused sigmoid-attention: 256 CTAs, 2 CTAs/SM, 3-stage pipeline
    attn_kernel<<<dim3(LQ_ / BM, B_), 256, SMEM_BYTES>>>(mask, out);
}